// round 11
// baseline (speedup 1.0000x reference)
#include <cuda_runtime.h>
#include <cuda_fp16.h>
#include <stdint.h>

#define P_PART 16
#define EDIM   512
#define HDIM   512
#define NENT   8192
#define NJOBS  2048
#define NCTAS  148

// ---------------- device scratch (pre-tiled, pre-swizzled) ----------------
__device__ __half g_X16[NENT * EDIM];            // [tile(128)][kc(8)][row(64)][kk(64)], SW128 per 8KB block
__device__ __half g_W0T[P_PART * EDIM * HDIM];   // [p][chunk(8)][n(512)][kk(64)], SW128; 64KB chunks
__device__ __half g_W1T[P_PART * HDIM * HDIM];
__device__ int    g_ctr;                         // persistent job counter

// ---------------- helpers ----------------
__device__ __forceinline__ uint32_t h2_bits(__half2 v) {
    return *reinterpret_cast<uint32_t*>(&v);
}
__device__ __forceinline__ uint32_t smem_u32(const void* p) {
    uint32_t a;
    asm("{ .reg .u64 t; cvta.to.shared.u64 t, %1; cvt.u32.u64 %0, t; }" : "=r"(a) : "l"(p));
    return a;
}
__host__ __device__ __forceinline__ uint32_t swz(uint32_t o) { return o ^ ((o >> 3) & 0x70); }

__device__ __forceinline__ void sts32(uint32_t a, uint32_t v) {
    asm volatile("st.shared.b32 [%0], %1;" :: "r"(a), "r"(v) : "memory");
}
__device__ __forceinline__ void ldmatrix_x4(uint32_t& r0, uint32_t& r1, uint32_t& r2,
                                            uint32_t& r3, uint32_t addr) {
    asm volatile("ldmatrix.sync.aligned.m8n8.x4.shared.b16 {%0,%1,%2,%3}, [%4];"
                 : "=r"(r0), "=r"(r1), "=r"(r2), "=r"(r3) : "r"(addr));
}

__device__ __forceinline__ void mbar_init(uint32_t a, uint32_t cnt) {
    asm volatile("mbarrier.init.shared.b64 [%0], %1;" :: "r"(a), "r"(cnt) : "memory");
}
__device__ __forceinline__ void mbar_expect(uint32_t a, uint32_t tx) {
    asm volatile("mbarrier.arrive.expect_tx.shared.b64 _, [%0], %1;" :: "r"(a), "r"(tx) : "memory");
}
__device__ __forceinline__ void mbar_arrive(uint32_t a) {
    asm volatile("mbarrier.arrive.shared.b64 _, [%0];" :: "r"(a) : "memory");
}
__device__ __forceinline__ void mbar_wait(uint32_t a, uint32_t parity) {
    uint32_t done = 0;
    while (!done) {
        asm volatile("{\n\t.reg .pred p;\n\t"
                     "mbarrier.try_wait.parity.acquire.cta.shared::cta.b64 p, [%1], %2, 0x989680;\n\t"
                     "selp.b32 %0,1,0,p;\n\t}"
                     : "=r"(done) : "r"(a), "r"(parity) : "memory");
    }
}
__device__ __forceinline__ void bulk_g2s(uint32_t dst, const void* src, uint32_t bytes,
                                         uint32_t mbar) {
    asm volatile("cp.async.bulk.shared::cluster.global.mbarrier::complete_tx::bytes "
                 "[%0], [%1], %2, [%3];"
                 :: "r"(dst), "l"(src), "r"(bytes), "r"(mbar) : "memory");
}

__device__ __forceinline__ void mma16816(float* d, const uint32_t* a, const uint32_t* b) {
    asm volatile(
        "mma.sync.aligned.m16n8k16.row.col.f32.f16.f16.f32 "
        "{%0,%1,%2,%3}, {%4,%5,%6,%7}, {%8,%9}, {%0,%1,%2,%3};"
        : "+f"(d[0]), "+f"(d[1]), "+f"(d[2]), "+f"(d[3])
        : "r"(a[0]), "r"(a[1]), "r"(a[2]), "r"(a[3]), "r"(b[0]), "r"(b[1]));
}

// ---------------- SMEM layout (bytes) ----------------
#define SM_A     0          // 8 blocks x [64 rows x 128B] = 65536 (x, then h)
#define SM_W     65536      // 2 x 65536 weight double buffer
#define SM_B0    196608
#define SM_B1    198656
#define SM_W2    200704
#define SM_LOG   202752     // 64 f32
#define SM_MBAR  203008     // mbA @+0; full[2] @+8; consumed[2] @+24; jnext @+48
#define SM_JOB   203056
#define SMEM_SZ  203072

// ---------------- prep kernels ----------------
__global__ void cvt_x_kernel(const float* __restrict__ x) {
    if (blockIdx.x == 0 && threadIdx.x == 0) g_ctr = NCTAS;   // seed persistent scheduler
    int s = blockIdx.x * blockDim.x + threadIdx.x;
    int n = s >> 6, sr = s & 63;
    const float4* src = reinterpret_cast<const float4*>(x + (size_t)n * 512 + sr * 8);
    float4 v0 = src[0], v1 = src[1];
    __half2 p0 = __floats2half2_rn(v0.x, v0.y);
    __half2 p1 = __floats2half2_rn(v0.z, v0.w);
    __half2 p2 = __floats2half2_rn(v1.x, v1.y);
    __half2 p3 = __floats2half2_rn(v1.z, v1.w);
    uint4 h;
    h.x = h2_bits(p0); h.y = h2_bits(p1); h.z = h2_bits(p2); h.w = h2_bits(p3);
    size_t off = (size_t)(n >> 6) * 65536 + (sr >> 3) * 8192
               + swz((uint32_t)((n & 63) * 128 + (sr & 7) * 16));
    *reinterpret_cast<uint4*>((char*)g_X16 + off) = h;
}

__global__ void cvt_wT_kernel(const float* __restrict__ W, int which) {
    __shared__ float tile[32][33];
    __half* T = which ? g_W1T : g_W0T;
    int p = blockIdx.z;
    int c0 = blockIdx.x * 32;   // n (output) base
    int r0 = blockIdx.y * 32;   // k (input) base
    const float* Wp = W + (size_t)p * 262144;
    char* Tp = (char*)T + (size_t)p * 524288;
    int tx = threadIdx.x, ty = threadIdx.y;  // (32, 8)
    #pragma unroll
    for (int r = 0; r < 32; r += 8)
        tile[ty + r][tx] = Wp[(size_t)(r0 + ty + r) * 512 + c0 + tx];
    __syncthreads();
    #pragma unroll
    for (int r = 0; r < 32; r += 8) {
        int n = c0 + ty + r;
        int k = r0 + tx;
        size_t off = (size_t)(k >> 6) * 65536 + swz((uint32_t)(n * 128 + (k & 63) * 2));
        *reinterpret_cast<__half*>(Tp + off) = __float2half(tile[tx][ty + r]);
    }
}

// ---------------- persistent fused MLP kernel ----------------
__global__ void __launch_bounds__(256, 1)
mlp_kernel(const float* __restrict__ b0, const float* __restrict__ b1,
           const float* __restrict__ W2v, const float* __restrict__ b2,
           float* __restrict__ out) {
    extern __shared__ __align__(1024) char smem[];
    const uint32_t sb = smem_u32(smem);
    const int tid = threadIdx.x, wid = tid >> 5, lid = tid & 31;

    float* b0s = (float*)(smem + SM_B0);
    float* b1s = (float*)(smem + SM_B1);
    float* w2s = (float*)(smem + SM_W2);
    float* logits = (float*)(smem + SM_LOG);
    int* jslot = (int*)(smem + SM_JOB);

    const uint32_t mbA = sb + SM_MBAR;
    const uint32_t mbF = sb + SM_MBAR + 8;     // full[b] at +8*b
    const uint32_t mbC = sb + SM_MBAR + 24;    // consumed[b] at +8*b

    if (tid == 0) {
        mbar_init(mbA, 1);
        mbar_init(mbF, 1);     mbar_init(mbF + 8, 1);
        mbar_init(mbC, 8);     mbar_init(mbC + 8, 8);
    }

    int job = blockIdx.x;                       // first job
    int p = job >> 7, tile = job & 127;

    if (tid == 0) jslot[0] = atomicAdd(&g_ctr, 1);
    for (int c = tid; c < 512; c += 256) {
        b0s[c] = b0[p * 512 + c];
        b1s[c] = b1[p * 512 + c];
        w2s[c] = W2v[p * 512 + c];
    }
    if (tid < 64) logits[tid] = b2[p];
    __syncthreads();                            // mbars + jslot + biases visible

    if (tid == 0) {
        const char* w0p = (const char*)g_W0T + (size_t)p * 524288;
        mbar_expect(mbA, 65536);
        bulk_g2s(sb + SM_A, (const char*)g_X16 + (size_t)tile * 65536, 65536, mbA);
        mbar_expect(mbF, 65536);
        bulk_g2s(sb + SM_W, w0p, 65536, mbF);
        mbar_expect(mbF + 8, 65536);
        bulk_g2s(sb + SM_W + 65536, w0p + 65536, 65536, mbF + 8);
    }

    const int arow = lid >> 2;
    const int acol = (lid & 3) * 2;
    const uint32_t a_lrow = (uint32_t)(lid & 15) * 128;
    const uint32_t a_lcol = (uint32_t)(lid >> 4) * 16;
    const int      b_nrow = wid * 64 + ((lid >> 4) << 3) + (lid & 7);
    const uint32_t b_lcol = (uint32_t)((lid >> 3) & 1) * 16;

    uint32_t phA = 0;
    uint32_t phF[2] = {0u, 0u};
    uint32_t phC[2] = {0u, 0u};

    while (true) {
        const char* w0p = (const char*)g_W0T + (size_t)p * 524288;
        const char* w1p = (const char*)g_W1T + (size_t)p * 524288;

        const int njob = jslot[0];              // set during previous iteration (barrier since)
        const bool has_next = njob < NJOBS;
        const int np_ = njob >> 7, ntile = njob & 127;
        const char* nw0p = (const char*)g_W0T + (size_t)np_ * 524288;

        float acc[4][8][4];
        #pragma unroll
        for (int mt = 0; mt < 4; mt++)
            #pragma unroll
            for (int nt = 0; nt < 8; nt++)
                #pragma unroll
                for (int j = 0; j < 4; j++) acc[mt][nt][j] = 0.f;

        mbar_wait(mbA, phA); phA ^= 1;

        for (int e = 0; e < 16; e++) {
            const int b = e & 1;
            mbar_wait(mbF + b * 8, phF[b]); phF[b] ^= 1;

            const uint32_t ab = sb + SM_A + (e & 7) * 8192;
            const uint32_t wb = sb + SM_W + b * 65536;

            #pragma unroll
            for (int ks = 0; ks < 4; ks++) {
                const uint32_t kb = (uint32_t)ks * 32;
                uint32_t aF[4][4];
                #pragma unroll
                for (int mt = 0; mt < 4; mt++)
                    ldmatrix_x4(aF[mt][0], aF[mt][1], aF[mt][2], aF[mt][3],
                                ab + mt * 2048 + swz(a_lrow + kb + a_lcol));
                uint32_t bF[8][2];
                #pragma unroll
                for (int np = 0; np < 4; np++) {
                    int nr = b_nrow + np * 16;
                    uint32_t addr = wb + (uint32_t)(nr >> 3) * 1024
                                  + swz((uint32_t)(nr & 7) * 128 + kb + b_lcol);
                    ldmatrix_x4(bF[2 * np][0], bF[2 * np][1],
                                bF[2 * np + 1][0], bF[2 * np + 1][1], addr);
                }
                #pragma unroll
                for (int mt = 0; mt < 4; mt++)
                    #pragma unroll
                    for (int nt = 0; nt < 8; nt++)
                        mma16816(acc[mt][nt], aF[mt], bF[nt]);
            }

            if (lid == 0) mbar_arrive(mbC + b * 8);

            // producer: chunk stream flows across tile boundaries
            if (tid == 0) {
                const int c = e + 2;
                const char* src = (const char*)0;
                if (c < 16)                      src = (c < 8) ? (w0p + (size_t)c * 65536)
                                                              : (w1p + (size_t)(c - 8) * 65536);
                else if (has_next && c < 18)     src = nw0p + (size_t)(c - 16) * 65536;
                if (src) {
                    mbar_wait(mbC + b * 8, phC[b]); phC[b] ^= 1;
                    mbar_expect(mbF + b * 8, 65536);
                    bulk_g2s(sb + SM_W + b * 65536, src, 65536, mbF + b * 8);
                }
            }

            // ---- layer-0 epilogue: bias+relu, h overwrites x in SMEM ----
            if (e == 7) {
                __syncthreads();
                #pragma unroll
                for (int mt = 0; mt < 4; mt++) {
                    #pragma unroll
                    for (int nt = 0; nt < 8; nt++) {
                        int row = mt * 16 + arow;
                        int col = wid * 64 + nt * 8 + acol;
                        uint32_t o = (uint32_t)(row * 128 + (col & 63) * 2);
                        uint32_t addr = sb + SM_A + (uint32_t)(col >> 6) * 8192 + swz(o);
                        float z0 = fmaxf(acc[mt][nt][0] + b0s[col],     0.f);
                        float z1 = fmaxf(acc[mt][nt][1] + b0s[col + 1], 0.f);
                        __half2 h01 = __floats2half2_rn(z0, z1);
                        sts32(addr, h2_bits(h01));
                        float z2 = fmaxf(acc[mt][nt][2] + b0s[col],     0.f);
                        float z3 = fmaxf(acc[mt][nt][3] + b0s[col + 1], 0.f);
                        __half2 h23 = __floats2half2_rn(z2, z3);
                        sts32(addr + 1024, h2_bits(h23));
                        acc[mt][nt][0] = 0.f; acc[mt][nt][1] = 0.f;
                        acc[mt][nt][2] = 0.f; acc[mt][nt][3] = 0.f;
                    }
                }
                __syncthreads();
            }
        }

        __syncthreads();   // all A reads done -> A region free
        if (tid == 0 && has_next) {
            mbar_expect(mbA, 65536);
            bulk_g2s(sb + SM_A, (const char*)g_X16 + (size_t)ntile * 65536, 65536, mbA);
        }
        if (tid == 0) jslot[0] = atomicAdd(&g_ctr, 1);   // fetch job after njob

        // ---- final epilogue: bias+relu, dot with W2, sigmoid ----
        #pragma unroll
        for (int mt = 0; mt < 4; mt++) {
            float s0 = 0.f, s1 = 0.f;
            #pragma unroll
            for (int nt = 0; nt < 8; nt++) {
                int col = wid * 64 + nt * 8 + acol;
                float w0c = w2s[col], w1c = w2s[col + 1];
                s0 += fmaxf(acc[mt][nt][0] + b1s[col],     0.f) * w0c
                    + fmaxf(acc[mt][nt][1] + b1s[col + 1], 0.f) * w1c;
                s1 += fmaxf(acc[mt][nt][2] + b1s[col],     0.f) * w0c
                    + fmaxf(acc[mt][nt][3] + b1s[col + 1], 0.f) * w1c;
            }
            int row = mt * 16 + arow;
            atomicAdd(&logits[row],     s0);
            atomicAdd(&logits[row + 8], s1);
        }
        __syncthreads();
        if (tid < 64)
            out[(size_t)(tile * 64 + tid) * 16 + p] = 1.f / (1.f + expf(-logits[tid]));

        if (!has_next) break;

        __syncthreads();   // out reads of logits done
        if (np_ != p) {
            for (int c = tid; c < 512; c += 256) {
                b0s[c] = b0[np_ * 512 + c];
                b1s[c] = b1[np_ * 512 + c];
                w2s[c] = W2v[np_ * 512 + c];
            }
        }
        if (tid < 64) logits[tid] = b2[np_];
        p = np_; tile = ntile; job = njob;
        // visibility of reloads is guaranteed by the barriers inside the next epoch loop
    }
}

// ---------------- launch ----------------
extern "C" void kernel_launch(void* const* d_in, const int* in_sizes, int n_in,
                              void* d_out, int out_size) {
    const float* X  = (const float*)d_in[0];
    const float* W0 = (const float*)d_in[1];
    const float* b0 = (const float*)d_in[2];
    const float* W1 = (const float*)d_in[3];
    const float* b1 = (const float*)d_in[4];
    const float* W2 = (const float*)d_in[5];
    const float* b2 = (const float*)d_in[6];
    float* out = (float*)d_out;

    cvt_x_kernel<<<(NENT * EDIM / 8) / 256, 256>>>(X);
    cvt_wT_kernel<<<dim3(16, 16, 16), dim3(32, 8)>>>(W0, 0);
    cvt_wT_kernel<<<dim3(16, 16, 16), dim3(32, 8)>>>(W1, 1);

    cudaFuncSetAttribute(mlp_kernel, cudaFuncAttributeMaxDynamicSharedMemorySize, SMEM_SZ);
    mlp_kernel<<<NCTAS, 256, SMEM_SZ>>>(b0, b1, W2, b2, out);
}

// round 12
// speedup vs baseline: 1.0188x; 1.0188x over previous
#include <cuda_runtime.h>
#include <cuda_fp16.h>
#include <stdint.h>

#define P_PART 16
#define EDIM   512
#define HDIM   512
#define NENT   8192

// ---------------- device scratch (pre-tiled, pre-swizzled) ----------------
__device__ __half g_X16[NENT * EDIM];            // [tile(128)][kc(8)][row(64)][kk(64)], SW128 per 8KB block
__device__ __half g_W0T[P_PART * EDIM * HDIM];   // [p][chunk(8)][n(512)][kk(64)], SW128; 64KB chunks
__device__ __half g_W1T[P_PART * HDIM * HDIM];

// ---------------- helpers ----------------
__device__ __forceinline__ uint32_t h2_bits(__half2 v) {
    return *reinterpret_cast<uint32_t*>(&v);
}
__device__ __forceinline__ uint32_t smem_u32(const void* p) {
    uint32_t a;
    asm("{ .reg .u64 t; cvta.to.shared.u64 t, %1; cvt.u32.u64 %0, t; }" : "=r"(a) : "l"(p));
    return a;
}
__host__ __device__ __forceinline__ uint32_t swz(uint32_t o) { return o ^ ((o >> 3) & 0x70); }

__device__ __forceinline__ void sts32(uint32_t a, uint32_t v) {
    asm volatile("st.shared.b32 [%0], %1;" :: "r"(a), "r"(v) : "memory");
}
__device__ __forceinline__ void ldmatrix_x4(uint32_t& r0, uint32_t& r1, uint32_t& r2,
                                            uint32_t& r3, uint32_t addr) {
    asm volatile("ldmatrix.sync.aligned.m8n8.x4.shared.b16 {%0,%1,%2,%3}, [%4];"
                 : "=r"(r0), "=r"(r1), "=r"(r2), "=r"(r3) : "r"(addr));
}

__device__ __forceinline__ void mbar_init(uint32_t a, uint32_t cnt) {
    asm volatile("mbarrier.init.shared.b64 [%0], %1;" :: "r"(a), "r"(cnt) : "memory");
}
__device__ __forceinline__ void mbar_expect(uint32_t a, uint32_t tx) {
    asm volatile("mbarrier.arrive.expect_tx.shared.b64 _, [%0], %1;" :: "r"(a), "r"(tx) : "memory");
}
__device__ __forceinline__ void mbar_arrive(uint32_t a) {
    asm volatile("mbarrier.arrive.shared.b64 _, [%0];" :: "r"(a) : "memory");
}
__device__ __forceinline__ void mbar_wait(uint32_t a, uint32_t parity) {
    uint32_t done = 0;
    while (!done) {
        asm volatile("{\n\t.reg .pred p;\n\t"
                     "mbarrier.try_wait.parity.acquire.cta.shared::cta.b64 p, [%1], %2, 0x989680;\n\t"
                     "selp.b32 %0,1,0,p;\n\t}"
                     : "=r"(done) : "r"(a), "r"(parity) : "memory");
    }
}
__device__ __forceinline__ void bulk_g2s(uint32_t dst, const void* src, uint32_t bytes,
                                         uint32_t mbar) {
    asm volatile("cp.async.bulk.shared::cluster.global.mbarrier::complete_tx::bytes "
                 "[%0], [%1], %2, [%3];"
                 :: "r"(dst), "l"(src), "r"(bytes), "r"(mbar) : "memory");
}

__device__ __forceinline__ void mma16816(float* d, const uint32_t* a, const uint32_t* b) {
    asm volatile(
        "mma.sync.aligned.m16n8k16.row.col.f32.f16.f16.f32 "
        "{%0,%1,%2,%3}, {%4,%5,%6,%7}, {%8,%9}, {%0,%1,%2,%3};"
        : "+f"(d[0]), "+f"(d[1]), "+f"(d[2]), "+f"(d[3])
        : "r"(a[0]), "r"(a[1]), "r"(a[2]), "r"(a[3]), "r"(b[0]), "r"(b[1]));
}

// ---------------- SMEM layout (bytes) ----------------
#define SM_A     0          // 8 blocks x [64 rows x 128B] = 65536 (x, then h)
#define SM_W     65536      // 2 x 65536 weight double buffer ([512 n x 128B] swizzled)
#define SM_B0    196608
#define SM_B1    198656
#define SM_W2    200704
#define SM_LOG   202752     // 64 f32
#define SM_MBAR  203008     // A mbar; full[2]; consumed[2]
#define SMEM_SZ  203072

// ---------------- fused prep kernel ----------------
// blocks [0, 2048): X fp32 -> fp16, tiled+swizzled
// blocks [2048, 10240): W0/W1 fp32 -> transposed fp16, tiled+swizzled
__global__ void prep_kernel(const float* __restrict__ X,
                            const float* __restrict__ W0,
                            const float* __restrict__ W1) {
    if (blockIdx.x < 2048) {
        int s = blockIdx.x * 256 + threadIdx.x;
        int n = s >> 6, sr = s & 63;
        const float4* src = reinterpret_cast<const float4*>(X + (size_t)n * 512 + sr * 8);
        float4 v0 = src[0], v1 = src[1];
        __half2 p0 = __floats2half2_rn(v0.x, v0.y);
        __half2 p1 = __floats2half2_rn(v0.z, v0.w);
        __half2 p2 = __floats2half2_rn(v1.x, v1.y);
        __half2 p3 = __floats2half2_rn(v1.z, v1.w);
        uint4 h;
        h.x = h2_bits(p0); h.y = h2_bits(p1); h.z = h2_bits(p2); h.w = h2_bits(p3);
        size_t off = (size_t)(n >> 6) * 65536 + (sr >> 3) * 8192
                   + swz((uint32_t)((n & 63) * 128 + (sr & 7) * 16));
        *reinterpret_cast<uint4*>((char*)g_X16 + off) = h;
        return;
    }
    __shared__ float tile[32][33];
    int bb = blockIdx.x - 2048;          // 0..8191
    int z  = bb & 31;                    // which*16 + p
    int xy = bb >> 5;                    // 0..255
    int which = z >> 4;
    int p = z & 15;
    const float* W = which ? W1 : W0;
    __half* T = which ? g_W1T : g_W0T;
    int c0 = (xy & 15) * 32;             // n (output) base
    int r0 = (xy >> 4) * 32;             // k (input) base
    const float* Wp = W + (size_t)p * 262144;
    char* Tp = (char*)T + (size_t)p * 524288;
    int tx = threadIdx.x & 31, ty = threadIdx.x >> 5;   // (32, 8)
    #pragma unroll
    for (int r = 0; r < 32; r += 8)
        tile[ty + r][tx] = Wp[(size_t)(r0 + ty + r) * 512 + c0 + tx];
    __syncthreads();
    #pragma unroll
    for (int r = 0; r < 32; r += 8) {
        int n = c0 + ty + r;
        int k = r0 + tx;
        size_t off = (size_t)(k >> 6) * 65536 + swz((uint32_t)(n * 128 + (k & 63) * 2));
        *reinterpret_cast<__half*>(Tp + off) = __float2half(tile[tx][ty + r]);
    }
}

// ---------------- fused MLP kernel (HMMA + ldmatrix + A-frag rotation) ----------------
__global__ void __launch_bounds__(256, 1)
mlp_kernel(const float* __restrict__ b0, const float* __restrict__ b1,
           const float* __restrict__ W2v, const float* __restrict__ b2,
           float* __restrict__ out) {
    extern __shared__ __align__(1024) char smem[];
    const uint32_t sb = smem_u32(smem);
    const int tid = threadIdx.x, wid = tid >> 5, lid = tid & 31;
    const int p = blockIdx.x;
    const int tile = blockIdx.y;
    const int n0 = tile * 64;

    float* b0s = (float*)(smem + SM_B0);
    float* b1s = (float*)(smem + SM_B1);
    float* w2s = (float*)(smem + SM_W2);
    float* logits = (float*)(smem + SM_LOG);

    const uint32_t mbA = sb + SM_MBAR;
    const uint32_t mbF = sb + SM_MBAR + 8;     // full[b] at +8*b
    const uint32_t mbC = sb + SM_MBAR + 24;    // consumed[b] at +8*b

    if (tid == 0) {
        mbar_init(mbA, 1);
        mbar_init(mbF, 1);     mbar_init(mbF + 8, 1);
        mbar_init(mbC, 8);     mbar_init(mbC + 8, 8);
    }
    __syncthreads();

    const char* w0p = (const char*)g_W0T + (size_t)p * 524288;
    const char* w1p = (const char*)g_W1T + (size_t)p * 524288;

    if (tid == 0) {
        mbar_expect(mbA, 65536);
        bulk_g2s(sb + SM_A, (const char*)g_X16 + (size_t)tile * 65536, 65536, mbA);
        mbar_expect(mbF, 65536);
        bulk_g2s(sb + SM_W, w0p, 65536, mbF);
        mbar_expect(mbF + 8, 65536);
        bulk_g2s(sb + SM_W + 65536, w0p + 65536, 65536, mbF + 8);
    }

    for (int c = tid; c < 512; c += 256) {
        b0s[c] = b0[p * 512 + c];
        b1s[c] = b1[p * 512 + c];
        w2s[c] = W2v[p * 512 + c];
    }
    if (tid < 64) logits[tid] = b2[p];
    __syncthreads();

    float acc[4][8][4];
    #pragma unroll
    for (int mt = 0; mt < 4; mt++)
        #pragma unroll
        for (int nt = 0; nt < 8; nt++)
            #pragma unroll
            for (int j = 0; j < 4; j++) acc[mt][nt][j] = 0.f;

    const int arow = lid >> 2;
    const int acol = (lid & 3) * 2;

    // ldmatrix per-lane address components
    const uint32_t a_lrow = (uint32_t)(lid & 15) * 128;
    const uint32_t a_lcol = (uint32_t)(lid >> 4) * 16;
    const int      b_nrow = wid * 64 + ((lid >> 4) << 3) + (lid & 7);
    const uint32_t b_lcol = (uint32_t)((lid >> 3) & 1) * 16;

    mbar_wait(mbA, 0);
    uint32_t phF[2] = {0u, 0u};
    uint32_t phC[2] = {0u, 0u};

    uint32_t aF[2][4][4];   // rotated A fragments

    for (int e = 0; e < 16; e++) {
        const int b = e & 1;
        const uint32_t ab = sb + SM_A + (e & 7) * 8192;

        // hoist ks=0 A-fragment loads above the weight full-wait (A is resident)
        #pragma unroll
        for (int mt = 0; mt < 4; mt++)
            ldmatrix_x4(aF[0][mt][0], aF[0][mt][1], aF[0][mt][2], aF[0][mt][3],
                        ab + mt * 2048 + swz(a_lrow + a_lcol));

        mbar_wait(mbF + b * 8, phF[b]); phF[b] ^= 1;
        const uint32_t wb = sb + SM_W + b * 65536;

        #pragma unroll
        for (int ks = 0; ks < 4; ks++) {
            const int cur = ks & 1, nxt = cur ^ 1;
            const uint32_t kb = (uint32_t)ks * 32;
            uint32_t bF[8][2];
            #pragma unroll
            for (int np = 0; np < 4; np++) {
                int nr = b_nrow + np * 16;
                uint32_t addr = wb + (uint32_t)(nr >> 3) * 1024
                              + swz((uint32_t)(nr & 7) * 128 + kb + b_lcol);
                ldmatrix_x4(bF[2 * np][0], bF[2 * np][1],
                            bF[2 * np + 1][0], bF[2 * np + 1][1], addr);
            }
            if (ks < 3) {
                const uint32_t kb2 = (uint32_t)(ks + 1) * 32;
                #pragma unroll
                for (int mt = 0; mt < 4; mt++)
                    ldmatrix_x4(aF[nxt][mt][0], aF[nxt][mt][1], aF[nxt][mt][2], aF[nxt][mt][3],
                                ab + mt * 2048 + swz(a_lrow + kb2 + a_lcol));
            } else {
                // all smem reads of this weight buffer issued -> release (arrive = release)
                if (lid == 0) mbar_arrive(mbC + b * 8);
            }
            #pragma unroll
            for (int mt = 0; mt < 4; mt++)
                #pragma unroll
                for (int nt = 0; nt < 8; nt++)
                    mma16816(acc[mt][nt], aF[cur][mt], bF[nt]);
        }

        // producer: recycle buffer b once all 8 warps consumed it
        if (tid == 0 && e + 2 < 16) {
            mbar_wait(mbC + b * 8, phC[b]); phC[b] ^= 1;
            const char* src = (e + 2 < 8) ? (w0p + (size_t)(e + 2) * 65536)
                                          : (w1p + (size_t)(e - 6) * 65536);
            mbar_expect(mbF + b * 8, 65536);
            bulk_g2s(sb + SM_W + b * 65536, src, 65536, mbF + b * 8);
        }

        // ---- layer-0 epilogue: bias+relu, h overwrites x in SMEM ----
        if (e == 7) {
            __syncthreads();
            #pragma unroll
            for (int mt = 0; mt < 4; mt++) {
                #pragma unroll
                for (int nt = 0; nt < 8; nt++) {
                    int row = mt * 16 + arow;
                    int col = wid * 64 + nt * 8 + acol;
                    uint32_t o = (uint32_t)(row * 128 + (col & 63) * 2);
                    uint32_t addr = sb + SM_A + (uint32_t)(col >> 6) * 8192 + swz(o);
                    float z0 = fmaxf(acc[mt][nt][0] + b0s[col],     0.f);
                    float z1 = fmaxf(acc[mt][nt][1] + b0s[col + 1], 0.f);
                    __half2 h01 = __floats2half2_rn(z0, z1);
                    sts32(addr, h2_bits(h01));
                    float z2 = fmaxf(acc[mt][nt][2] + b0s[col],     0.f);
                    float z3 = fmaxf(acc[mt][nt][3] + b0s[col + 1], 0.f);
                    __half2 h23 = __floats2half2_rn(z2, z3);
                    sts32(addr + 1024, h2_bits(h23));
                    acc[mt][nt][0] = 0.f; acc[mt][nt][1] = 0.f;
                    acc[mt][nt][2] = 0.f; acc[mt][nt][3] = 0.f;
                }
            }
            __syncthreads();
        }
    }

    // ---- final epilogue: bias+relu, dot with W2, sigmoid ----
    #pragma unroll
    for (int mt = 0; mt < 4; mt++) {
        float s0 = 0.f, s1 = 0.f;
        #pragma unroll
        for (int nt = 0; nt < 8; nt++) {
            int col = wid * 64 + nt * 8 + acol;
            float w0c = w2s[col], w1c = w2s[col + 1];
            s0 += fmaxf(acc[mt][nt][0] + b1s[col],     0.f) * w0c
                + fmaxf(acc[mt][nt][1] + b1s[col + 1], 0.f) * w1c;
            s1 += fmaxf(acc[mt][nt][2] + b1s[col],     0.f) * w0c
                + fmaxf(acc[mt][nt][3] + b1s[col + 1], 0.f) * w1c;
        }
        int row = mt * 16 + arow;
        atomicAdd(&logits[row],     s0);
        atomicAdd(&logits[row + 8], s1);
    }
    __syncthreads();
    if (tid < 64)
        out[(size_t)(n0 + tid) * 16 + p] = 1.f / (1.f + expf(-logits[tid]));
}

// ---------------- launch ----------------
extern "C" void kernel_launch(void* const* d_in, const int* in_sizes, int n_in,
                              void* d_out, int out_size) {
    const float* X  = (const float*)d_in[0];
    const float* W0 = (const float*)d_in[1];
    const float* b0 = (const float*)d_in[2];
    const float* W1 = (const float*)d_in[3];
    const float* b1 = (const float*)d_in[4];
    const float* W2 = (const float*)d_in[5];
    const float* b2 = (const float*)d_in[6];
    float* out = (float*)d_out;

    prep_kernel<<<10240, 256>>>(X, W0, W1);

    cudaFuncSetAttribute(mlp_kernel, cudaFuncAttributeMaxDynamicSharedMemorySize, SMEM_SZ);
    mlp_kernel<<<dim3(P_PART, NENT / 64), 256, SMEM_SZ>>>(b0, b1, W2, b2, out);
}

// round 13
// speedup vs baseline: 1.0223x; 1.0035x over previous
#include <cuda_runtime.h>
#include <cuda_fp16.h>
#include <stdint.h>

#define P_PART 16
#define EDIM   512
#define HDIM   512
#define NENT   8192

// ---------------- device scratch (pre-tiled, pre-swizzled) ----------------
__device__ __half g_X16[NENT * EDIM];            // [tile(256)][kc(8)][row(32)][kk(64)], SW128 per 4KB block
__device__ __half g_W0T[P_PART * EDIM * HDIM];   // [p][chunk(16)][n(512)][kk(32)], SW64; 32KB chunks
__device__ __half g_W1T[P_PART * HDIM * HDIM];

// ---------------- helpers ----------------
__device__ __forceinline__ uint32_t h2_bits(__half2 v) {
    return *reinterpret_cast<uint32_t*>(&v);
}
__device__ __forceinline__ uint32_t smem_u32(const void* p) {
    uint32_t a;
    asm("{ .reg .u64 t; cvta.to.shared.u64 t, %1; cvt.u32.u64 %0, t; }" : "=r"(a) : "l"(p));
    return a;
}
__host__ __device__ __forceinline__ uint32_t swz(uint32_t o)   { return o ^ ((o >> 3) & 0x70); }
__host__ __device__ __forceinline__ uint32_t swz64(uint32_t o) { return o ^ ((o >> 3) & 0x30); }

__device__ __forceinline__ void sts32(uint32_t a, uint32_t v) {
    asm volatile("st.shared.b32 [%0], %1;" :: "r"(a), "r"(v) : "memory");
}
__device__ __forceinline__ void ldmatrix_x4(uint32_t& r0, uint32_t& r1, uint32_t& r2,
                                            uint32_t& r3, uint32_t addr) {
    asm volatile("ldmatrix.sync.aligned.m8n8.x4.shared.b16 {%0,%1,%2,%3}, [%4];"
                 : "=r"(r0), "=r"(r1), "=r"(r2), "=r"(r3) : "r"(addr));
}

__device__ __forceinline__ void mbar_init(uint32_t a, uint32_t cnt) {
    asm volatile("mbarrier.init.shared.b64 [%0], %1;" :: "r"(a), "r"(cnt) : "memory");
}
__device__ __forceinline__ void mbar_expect(uint32_t a, uint32_t tx) {
    asm volatile("mbarrier.arrive.expect_tx.shared.b64 _, [%0], %1;" :: "r"(a), "r"(tx) : "memory");
}
__device__ __forceinline__ void mbar_arrive(uint32_t a) {
    asm volatile("mbarrier.arrive.shared.b64 _, [%0];" :: "r"(a) : "memory");
}
__device__ __forceinline__ void mbar_wait(uint32_t a, uint32_t parity) {
    uint32_t done = 0;
    while (!done) {
        asm volatile("{\n\t.reg .pred p;\n\t"
                     "mbarrier.try_wait.parity.acquire.cta.shared::cta.b64 p, [%1], %2, 0x989680;\n\t"
                     "selp.b32 %0,1,0,p;\n\t}"
                     : "=r"(done) : "r"(a), "r"(parity) : "memory");
    }
}
__device__ __forceinline__ void bulk_g2s(uint32_t dst, const void* src, uint32_t bytes,
                                         uint32_t mbar) {
    asm volatile("cp.async.bulk.shared::cluster.global.mbarrier::complete_tx::bytes "
                 "[%0], [%1], %2, [%3];"
                 :: "r"(dst), "l"(src), "r"(bytes), "r"(mbar) : "memory");
}

__device__ __forceinline__ void mma16816(float* d, const uint32_t* a, const uint32_t* b) {
    asm volatile(
        "mma.sync.aligned.m16n8k16.row.col.f32.f16.f16.f32 "
        "{%0,%1,%2,%3}, {%4,%5,%6,%7}, {%8,%9}, {%0,%1,%2,%3};"
        : "+f"(d[0]), "+f"(d[1]), "+f"(d[2]), "+f"(d[3])
        : "r"(a[0]), "r"(a[1]), "r"(a[2]), "r"(a[3]), "r"(b[0]), "r"(b[1]));
}

// ---------------- SMEM layout (bytes, per 128-thread CTA) ----------------
#define SM_A     0          // 8 blocks x [32 rows x 128B] = 32768 (x, then h), SW128
#define SM_W     32768      // 2 x 32768 weight double buffer ([512 n x 64B] SW64)
#define SM_B0    98304
#define SM_B1    100352
#define SM_W2    102400
#define SM_LOG   104448     // 32 f32
#define SM_MBAR  104576     // mbA @+0; full[2] @+8; consumed[2] @+24
#define SMEM_SZ  104704

// ---------------- fused prep kernel ----------------
// blocks [0, 2048): X fp32 -> fp16, 32-row tiles, SW128 4KB blocks
// blocks [2048, 10240): W0/W1 -> transposed fp16, SW64 32KB chunks
__global__ void prep_kernel(const float* __restrict__ X,
                            const float* __restrict__ W0,
                            const float* __restrict__ W1) {
    if (blockIdx.x < 2048) {
        int s = blockIdx.x * 256 + threadIdx.x;
        int n = s >> 6, sr = s & 63;
        const float4* src = reinterpret_cast<const float4*>(X + (size_t)n * 512 + sr * 8);
        float4 v0 = src[0], v1 = src[1];
        __half2 p0 = __floats2half2_rn(v0.x, v0.y);
        __half2 p1 = __floats2half2_rn(v0.z, v0.w);
        __half2 p2 = __floats2half2_rn(v1.x, v1.y);
        __half2 p3 = __floats2half2_rn(v1.z, v1.w);
        uint4 h;
        h.x = h2_bits(p0); h.y = h2_bits(p1); h.z = h2_bits(p2); h.w = h2_bits(p3);
        size_t off = (size_t)(n >> 5) * 32768 + (sr >> 3) * 4096
                   + swz((uint32_t)((n & 31) * 128 + (sr & 7) * 16));
        *reinterpret_cast<uint4*>((char*)g_X16 + off) = h;
        return;
    }
    __shared__ float tile[32][33];
    int bb = blockIdx.x - 2048;
    int z  = bb & 31;
    int xy = bb >> 5;
    int which = z >> 4;
    int p = z & 15;
    const float* W = which ? W1 : W0;
    __half* T = which ? g_W1T : g_W0T;
    int c0 = (xy & 15) * 32;             // n (output) base
    int r0 = (xy >> 4) * 32;             // k (input) base
    const float* Wp = W + (size_t)p * 262144;
    char* Tp = (char*)T + (size_t)p * 524288;
    int tx = threadIdx.x & 31, ty = threadIdx.x >> 5;
    #pragma unroll
    for (int r = 0; r < 32; r += 8)
        tile[ty + r][tx] = Wp[(size_t)(r0 + ty + r) * 512 + c0 + tx];
    __syncthreads();
    #pragma unroll
    for (int r = 0; r < 32; r += 8) {
        int n = c0 + ty + r;
        int k = r0 + tx;
        size_t off = (size_t)(k >> 5) * 32768 + swz64((uint32_t)(n * 64 + (k & 31) * 2));
        *reinterpret_cast<__half*>(Tp + off) = __float2half(tile[tx][ty + r]);
    }
}

// ---------------- fused MLP kernel: 128 threads, 2 CTAs/SM ----------------
__global__ void __launch_bounds__(128, 2)
mlp_kernel(const float* __restrict__ b0, const float* __restrict__ b1,
           const float* __restrict__ W2v, const float* __restrict__ b2,
           float* __restrict__ out) {
    extern __shared__ __align__(1024) char smem[];
    const uint32_t sb = smem_u32(smem);
    const int tid = threadIdx.x, wid = tid >> 5, lid = tid & 31;
    const int p = blockIdx.x;
    const int tile = blockIdx.y;
    const int n0 = tile * 32;

    float* b0s = (float*)(smem + SM_B0);
    float* b1s = (float*)(smem + SM_B1);
    float* w2s = (float*)(smem + SM_W2);
    float* logits = (float*)(smem + SM_LOG);

    const uint32_t mbA = sb + SM_MBAR;
    const uint32_t mbF = sb + SM_MBAR + 8;     // full[b] at +8*b
    const uint32_t mbC = sb + SM_MBAR + 24;    // consumed[b] at +8*b

    if (tid == 0) {
        mbar_init(mbA, 1);
        mbar_init(mbF, 1);     mbar_init(mbF + 8, 1);
        mbar_init(mbC, 4);     mbar_init(mbC + 8, 4);
    }
    __syncthreads();

    const char* w0p = (const char*)g_W0T + (size_t)p * 524288;
    const char* w1p = (const char*)g_W1T + (size_t)p * 524288;

    if (tid == 0) {
        mbar_expect(mbA, 32768);
        bulk_g2s(sb + SM_A, (const char*)g_X16 + (size_t)tile * 32768, 32768, mbA);
        mbar_expect(mbF, 32768);
        bulk_g2s(sb + SM_W, w0p, 32768, mbF);
        mbar_expect(mbF + 8, 32768);
        bulk_g2s(sb + SM_W + 32768, w0p + 32768, 32768, mbF + 8);
    }

    for (int c = tid; c < 512; c += 128) {
        b0s[c] = b0[p * 512 + c];
        b1s[c] = b1[p * 512 + c];
        w2s[c] = W2v[p * 512 + c];
    }
    if (tid < 32) logits[tid] = b2[p];
    __syncthreads();

    float acc[2][16][4];
    #pragma unroll
    for (int mt = 0; mt < 2; mt++)
        #pragma unroll
        for (int nt = 0; nt < 16; nt++)
            #pragma unroll
            for (int j = 0; j < 4; j++) acc[mt][nt][j] = 0.f;

    const int arow = lid >> 2;
    const int acol = (lid & 3) * 2;

    // ldmatrix per-lane address components
    const uint32_t a_lrow = (uint32_t)(lid & 15) * 128;
    const uint32_t a_lcol = (uint32_t)(lid >> 4) * 16;
    const int      b_nrow = wid * 128 + ((lid >> 4) << 3) + (lid & 7);
    const uint32_t b_lcol = (uint32_t)((lid >> 3) & 1) * 16;

    mbar_wait(mbA, 0);
    uint32_t phF[2] = {0u, 0u};
    uint32_t phC[2] = {0u, 0u};

    for (int e = 0; e < 32; e++) {
        const int b = e & 1;
        mbar_wait(mbF + b * 8, phF[b]); phF[b] ^= 1;

        const uint32_t ab  = sb + SM_A + ((e & 15) >> 1) * 4096;
        const uint32_t kbA = (uint32_t)(e & 1) * 64;
        const uint32_t wb  = sb + SM_W + b * 32768;

        #pragma unroll
        for (int ks = 0; ks < 2; ks++) {
            const uint32_t kb = (uint32_t)ks * 32;
            uint32_t aF[2][4];
            #pragma unroll
            for (int mt = 0; mt < 2; mt++)
                ldmatrix_x4(aF[mt][0], aF[mt][1], aF[mt][2], aF[mt][3],
                            ab + mt * 2048 + swz(a_lrow + kbA + kb + a_lcol));
            uint32_t bF[16][2];
            #pragma unroll
            for (int np = 0; np < 8; np++) {
                uint32_t nr = (uint32_t)(b_nrow + np * 16);
                uint32_t addr = wb + swz64(nr * 64 + kb + b_lcol);
                ldmatrix_x4(bF[2 * np][0], bF[2 * np][1],
                            bF[2 * np + 1][0], bF[2 * np + 1][1], addr);
            }
            // after last smem read of this chunk, release the slot
            if (ks == 1 && lid == 0) mbar_arrive(mbC + b * 8);
            #pragma unroll
            for (int mt = 0; mt < 2; mt++)
                #pragma unroll
                for (int nt = 0; nt < 16; nt++)
                    mma16816(acc[mt][nt], aF[mt], bF[nt]);
        }

        // producer: recycle buffer b once all 4 warps consumed it
        if (tid == 0 && e + 2 < 32) {
            mbar_wait(mbC + b * 8, phC[b]); phC[b] ^= 1;
            const int c = e + 2;
            const char* src = (c < 16) ? (w0p + (size_t)c * 32768)
                                       : (w1p + (size_t)(c - 16) * 32768);
            mbar_expect(mbF + b * 8, 32768);
            bulk_g2s(sb + SM_W + b * 32768, src, 32768, mbF + b * 8);
        }

        // ---- layer-0 epilogue: bias+relu, h overwrites x in SMEM ----
        if (e == 15) {
            __syncthreads();
            #pragma unroll
            for (int mt = 0; mt < 2; mt++) {
                #pragma unroll
                for (int nt = 0; nt < 16; nt++) {
                    int row = mt * 16 + arow;
                    int col = wid * 128 + nt * 8 + acol;
                    uint32_t o = (uint32_t)(row * 128 + (col & 63) * 2);
                    uint32_t addr = sb + SM_A + (uint32_t)(col >> 6) * 4096 + swz(o);
                    float z0 = fmaxf(acc[mt][nt][0] + b0s[col],     0.f);
                    float z1 = fmaxf(acc[mt][nt][1] + b0s[col + 1], 0.f);
                    __half2 h01 = __floats2half2_rn(z0, z1);
                    sts32(addr, h2_bits(h01));
                    float z2 = fmaxf(acc[mt][nt][2] + b0s[col],     0.f);
                    float z3 = fmaxf(acc[mt][nt][3] + b0s[col + 1], 0.f);
                    __half2 h23 = __floats2half2_rn(z2, z3);
                    sts32(addr + 1024, h2_bits(h23));
                    acc[mt][nt][0] = 0.f; acc[mt][nt][1] = 0.f;
                    acc[mt][nt][2] = 0.f; acc[mt][nt][3] = 0.f;
                }
            }
            __syncthreads();
        }
    }

    // ---- final epilogue: bias+relu, dot with W2, sigmoid ----
    #pragma unroll
    for (int mt = 0; mt < 2; mt++) {
        float s0 = 0.f, s1 = 0.f;
        #pragma unroll
        for (int nt = 0; nt < 16; nt++) {
            int col = wid * 128 + nt * 8 + acol;
            float w0c = w2s[col], w1c = w2s[col + 1];
            s0 += fmaxf(acc[mt][nt][0] + b1s[col],     0.f) * w0c
                + fmaxf(acc[mt][nt][1] + b1s[col + 1], 0.f) * w1c;
            s1 += fmaxf(acc[mt][nt][2] + b1s[col],     0.f) * w0c
                + fmaxf(acc[mt][nt][3] + b1s[col + 1], 0.f) * w1c;
        }
        int row = mt * 16 + arow;
        atomicAdd(&logits[row],     s0);
        atomicAdd(&logits[row + 8], s1);
    }
    __syncthreads();
    if (tid < 32)
        out[(size_t)(n0 + tid) * 16 + p] = 1.f / (1.f + expf(-logits[tid]));
}

// ---------------- launch ----------------
extern "C" void kernel_launch(void* const* d_in, const int* in_sizes, int n_in,
                              void* d_out, int out_size) {
    const float* X  = (const float*)d_in[0];
    const float* W0 = (const float*)d_in[1];
    const float* b0 = (const float*)d_in[2];
    const float* W1 = (const float*)d_in[3];
    const float* b1 = (const float*)d_in[4];
    const float* W2 = (const float*)d_in[5];
    const float* b2 = (const float*)d_in[6];
    float* out = (float*)d_out;

    prep_kernel<<<10240, 256>>>(X, W0, W1);

    cudaFuncSetAttribute(mlp_kernel, cudaFuncAttributeMaxDynamicSharedMemorySize, SMEM_SZ);
    mlp_kernel<<<dim3(P_PART, NENT / 32), 128, SMEM_SZ>>>(b0, b1, W2, b2, out);
}

// round 14
// speedup vs baseline: 1.0541x; 1.0311x over previous
#include <cuda_runtime.h>
#include <cuda_fp16.h>
#include <stdint.h>

#define P_PART 16
#define EDIM   512
#define HDIM   512
#define NENT   8192

// ---------------- device scratch (pre-tiled, pre-swizzled) ----------------
__device__ __half g_X16[NENT * EDIM];            // [tile(128)][kc(8)][row(64)][kk(64)], SW128 per 8KB block
__device__ __half g_W0T[P_PART * EDIM * HDIM];   // [p][chunk(8)][n(512)][kk(64)], SW128; 64KB chunks
__device__ __half g_W1T[P_PART * HDIM * HDIM];

// ---------------- helpers ----------------
__device__ __forceinline__ uint32_t h2_bits(__half2 v) {
    return *reinterpret_cast<uint32_t*>(&v);
}
__device__ __forceinline__ __half2 bits_h2(uint32_t v) {
    return *reinterpret_cast<__half2*>(&v);
}
__device__ __forceinline__ uint32_t smem_u32(const void* p) {
    uint32_t a;
    asm("{ .reg .u64 t; cvta.to.shared.u64 t, %1; cvt.u32.u64 %0, t; }" : "=r"(a) : "l"(p));
    return a;
}
__host__ __device__ __forceinline__ uint32_t swz(uint32_t o) { return o ^ ((o >> 3) & 0x70); }

__device__ __forceinline__ void sts32(uint32_t a, uint32_t v) {
    asm volatile("st.shared.b32 [%0], %1;" :: "r"(a), "r"(v) : "memory");
}
__device__ __forceinline__ void ldmatrix_x4(uint32_t& r0, uint32_t& r1, uint32_t& r2,
                                            uint32_t& r3, uint32_t addr) {
    asm volatile("ldmatrix.sync.aligned.m8n8.x4.shared.b16 {%0,%1,%2,%3}, [%4];"
                 : "=r"(r0), "=r"(r1), "=r"(r2), "=r"(r3) : "r"(addr));
}

__device__ __forceinline__ void mbar_init(uint32_t a, uint32_t cnt) {
    asm volatile("mbarrier.init.shared.b64 [%0], %1;" :: "r"(a), "r"(cnt) : "memory");
}
__device__ __forceinline__ void mbar_expect(uint32_t a, uint32_t tx) {
    asm volatile("mbarrier.arrive.expect_tx.shared.b64 _, [%0], %1;" :: "r"(a), "r"(tx) : "memory");
}
__device__ __forceinline__ void mbar_arrive(uint32_t a) {
    asm volatile("mbarrier.arrive.shared.b64 _, [%0];" :: "r"(a) : "memory");
}
__device__ __forceinline__ void mbar_wait(uint32_t a, uint32_t parity) {
    uint32_t done = 0;
    while (!done) {
        asm volatile("{\n\t.reg .pred p;\n\t"
                     "mbarrier.try_wait.parity.acquire.cta.shared::cta.b64 p, [%1], %2, 0x989680;\n\t"
                     "selp.b32 %0,1,0,p;\n\t}"
                     : "=r"(done) : "r"(a), "r"(parity) : "memory");
    }
}
__device__ __forceinline__ void bulk_g2s(uint32_t dst, const void* src, uint32_t bytes,
                                         uint32_t mbar) {
    asm volatile("cp.async.bulk.shared::cluster.global.mbarrier::complete_tx::bytes "
                 "[%0], [%1], %2, [%3];"
                 :: "r"(dst), "l"(src), "r"(bytes), "r"(mbar) : "memory");
}

// fp16-accumulate MMA: D(f16x2 x2) = A*B + D
__device__ __forceinline__ void mma16816_h(uint32_t* d, const uint32_t* a, const uint32_t* b) {
    asm volatile(
        "mma.sync.aligned.m16n8k16.row.col.f16.f16.f16.f16 "
        "{%0,%1}, {%2,%3,%4,%5}, {%6,%7}, {%0,%1};"
        : "+r"(d[0]), "+r"(d[1])
        : "r"(a[0]), "r"(a[1]), "r"(a[2]), "r"(a[3]), "r"(b[0]), "r"(b[1]));
}

// ---------------- SMEM layout (bytes) ----------------
#define SM_A     0          // 8 blocks x [64 rows x 128B] = 65536 (x, then h)
#define SM_W     65536      // 2 x 65536 weight double buffer ([512 n x 128B] swizzled)
#define SM_B0    196608
#define SM_B1    198656
#define SM_W2    200704
#define SM_LOG   202752     // 64 f32
#define SM_MBAR  203008     // A mbar; full[2]; consumed[2]
#define SMEM_SZ  203072

// ---------------- fused prep kernel ----------------
__global__ void prep_kernel(const float* __restrict__ X,
                            const float* __restrict__ W0,
                            const float* __restrict__ W1) {
    if (blockIdx.x < 2048) {
        int s = blockIdx.x * 256 + threadIdx.x;
        int n = s >> 6, sr = s & 63;
        const float4* src = reinterpret_cast<const float4*>(X + (size_t)n * 512 + sr * 8);
        float4 v0 = src[0], v1 = src[1];
        __half2 p0 = __floats2half2_rn(v0.x, v0.y);
        __half2 p1 = __floats2half2_rn(v0.z, v0.w);
        __half2 p2 = __floats2half2_rn(v1.x, v1.y);
        __half2 p3 = __floats2half2_rn(v1.z, v1.w);
        uint4 h;
        h.x = h2_bits(p0); h.y = h2_bits(p1); h.z = h2_bits(p2); h.w = h2_bits(p3);
        size_t off = (size_t)(n >> 6) * 65536 + (sr >> 3) * 8192
                   + swz((uint32_t)((n & 63) * 128 + (sr & 7) * 16));
        *reinterpret_cast<uint4*>((char*)g_X16 + off) = h;
        return;
    }
    __shared__ float tile[32][33];
    int bb = blockIdx.x - 2048;
    int z  = bb & 31;
    int xy = bb >> 5;
    int which = z >> 4;
    int p = z & 15;
    const float* W = which ? W1 : W0;
    __half* T = which ? g_W1T : g_W0T;
    int c0 = (xy & 15) * 32;             // n (output) base
    int r0 = (xy >> 4) * 32;             // k (input) base
    const float* Wp = W + (size_t)p * 262144;
    char* Tp = (char*)T + (size_t)p * 524288;
    int tx = threadIdx.x & 31, ty = threadIdx.x >> 5;
    #pragma unroll
    for (int r = 0; r < 32; r += 8)
        tile[ty + r][tx] = Wp[(size_t)(r0 + ty + r) * 512 + c0 + tx];
    __syncthreads();
    #pragma unroll
    for (int r = 0; r < 32; r += 8) {
        int n = c0 + ty + r;
        int k = r0 + tx;
        size_t off = (size_t)(k >> 6) * 65536 + swz((uint32_t)(n * 128 + (k & 63) * 2));
        *reinterpret_cast<__half*>(Tp + off) = __float2half(tile[tx][ty + r]);
    }
}

// ---------------- fused MLP kernel (HMMA fp16-acc probe) ----------------
__global__ void __launch_bounds__(256, 1)
mlp_kernel(const float* __restrict__ b0, const float* __restrict__ b1,
           const float* __restrict__ W2v, const float* __restrict__ b2,
           float* __restrict__ out) {
    extern __shared__ __align__(1024) char smem[];
    const uint32_t sb = smem_u32(smem);
    const int tid = threadIdx.x, wid = tid >> 5, lid = tid & 31;
    const int p = blockIdx.x;
    const int tile = blockIdx.y;
    const int n0 = tile * 64;

    float* b0s = (float*)(smem + SM_B0);
    float* b1s = (float*)(smem + SM_B1);
    float* w2s = (float*)(smem + SM_W2);
    float* logits = (float*)(smem + SM_LOG);

    const uint32_t mbA = sb + SM_MBAR;
    const uint32_t mbF = sb + SM_MBAR + 8;     // full[b] at +8*b
    const uint32_t mbC = sb + SM_MBAR + 24;    // consumed[b] at +8*b

    if (tid == 0) {
        mbar_init(mbA, 1);
        mbar_init(mbF, 1);     mbar_init(mbF + 8, 1);
        mbar_init(mbC, 8);     mbar_init(mbC + 8, 8);
    }
    __syncthreads();

    const char* w0p = (const char*)g_W0T + (size_t)p * 524288;
    const char* w1p = (const char*)g_W1T + (size_t)p * 524288;

    if (tid == 0) {
        mbar_expect(mbA, 65536);
        bulk_g2s(sb + SM_A, (const char*)g_X16 + (size_t)tile * 65536, 65536, mbA);
        mbar_expect(mbF, 65536);
        bulk_g2s(sb + SM_W, w0p, 65536, mbF);
        mbar_expect(mbF + 8, 65536);
        bulk_g2s(sb + SM_W + 65536, w0p + 65536, 65536, mbF + 8);
    }

    for (int c = tid; c < 512; c += 256) {
        b0s[c] = b0[p * 512 + c];
        b1s[c] = b1[p * 512 + c];
        w2s[c] = W2v[p * 512 + c];
    }
    if (tid < 64) logits[tid] = b2[p];
    __syncthreads();

    // fp16x2 accumulators: [mt][nt][half-pair]; 0 bits == (+0,+0)
    uint32_t acc[4][8][2];
    #pragma unroll
    for (int mt = 0; mt < 4; mt++)
        #pragma unroll
        for (int nt = 0; nt < 8; nt++) { acc[mt][nt][0] = 0u; acc[mt][nt][1] = 0u; }

    const int arow = lid >> 2;
    const int acol = (lid & 3) * 2;

    const uint32_t a_lrow = (uint32_t)(lid & 15) * 128;
    const uint32_t a_lcol = (uint32_t)(lid >> 4) * 16;
    const int      b_nrow = wid * 64 + ((lid >> 4) << 3) + (lid & 7);
    const uint32_t b_lcol = (uint32_t)((lid >> 3) & 1) * 16;

    mbar_wait(mbA, 0);
    uint32_t phF[2] = {0u, 0u};
    uint32_t phC[2] = {0u, 0u};

    const __half2 hzero = __float2half2_rn(0.f);

    for (int e = 0; e < 16; e++) {
        const int b = e & 1;
        mbar_wait(mbF + b * 8, phF[b]); phF[b] ^= 1;

        const uint32_t ab = sb + SM_A + (e & 7) * 8192;
        const uint32_t wb = sb + SM_W + b * 65536;

        #pragma unroll
        for (int ks = 0; ks < 4; ks++) {
            const uint32_t kb = (uint32_t)ks * 32;
            uint32_t aF[4][4];
            #pragma unroll
            for (int mt = 0; mt < 4; mt++)
                ldmatrix_x4(aF[mt][0], aF[mt][1], aF[mt][2], aF[mt][3],
                            ab + mt * 2048 + swz(a_lrow + kb + a_lcol));
            uint32_t bF[8][2];
            #pragma unroll
            for (int np = 0; np < 4; np++) {
                int nr = b_nrow + np * 16;
                uint32_t addr = wb + (uint32_t)(nr >> 3) * 1024
                              + swz((uint32_t)(nr & 7) * 128 + kb + b_lcol);
                ldmatrix_x4(bF[2 * np][0], bF[2 * np][1],
                            bF[2 * np + 1][0], bF[2 * np + 1][1], addr);
            }
            if (ks == 3 && lid == 0) mbar_arrive(mbC + b * 8);
            #pragma unroll
            for (int mt = 0; mt < 4; mt++)
                #pragma unroll
                for (int nt = 0; nt < 8; nt++)
                    mma16816_h(acc[mt][nt], aF[mt], bF[nt]);
        }

        // producer: recycle buffer b once all 8 warps consumed it
        if (tid == 0 && e + 2 < 16) {
            mbar_wait(mbC + b * 8, phC[b]); phC[b] ^= 1;
            const char* src = (e + 2 < 8) ? (w0p + (size_t)(e + 2) * 65536)
                                          : (w1p + (size_t)(e - 6) * 65536);
            mbar_expect(mbF + b * 8, 65536);
            bulk_g2s(sb + SM_W + b * 65536, src, 65536, mbF + b * 8);
        }

        // ---- layer-0 epilogue: bias+relu in half2, h overwrites x in SMEM ----
        if (e == 7) {
            __syncthreads();
            #pragma unroll
            for (int mt = 0; mt < 4; mt++) {
                #pragma unroll
                for (int nt = 0; nt < 8; nt++) {
                    int row = mt * 16 + arow;
                    int col = wid * 64 + nt * 8 + acol;
                    uint32_t o = (uint32_t)(row * 128 + (col & 63) * 2);
                    uint32_t addr = sb + SM_A + (uint32_t)(col >> 6) * 8192 + swz(o);
                    __half2 bias2 = __floats2half2_rn(b0s[col], b0s[col + 1]);
                    __half2 h01 = __hmax2(__hadd2(bits_h2(acc[mt][nt][0]), bias2), hzero);
                    __half2 h23 = __hmax2(__hadd2(bits_h2(acc[mt][nt][1]), bias2), hzero);
                    sts32(addr, h2_bits(h01));
                    sts32(addr + 1024, h2_bits(h23));
                    acc[mt][nt][0] = 0u; acc[mt][nt][1] = 0u;
                }
            }
            __syncthreads();
        }
    }

    // ---- final epilogue: bias+relu (half2), dot with W2 in fp32, sigmoid ----
    #pragma unroll
    for (int mt = 0; mt < 4; mt++) {
        float s0 = 0.f, s1 = 0.f;
        #pragma unroll
        for (int nt = 0; nt < 8; nt++) {
            int col = wid * 64 + nt * 8 + acol;
            __half2 bias2 = __floats2half2_rn(b1s[col], b1s[col + 1]);
            float2 z01 = __half22float2(__hmax2(__hadd2(bits_h2(acc[mt][nt][0]), bias2), hzero));
            float2 z23 = __half22float2(__hmax2(__hadd2(bits_h2(acc[mt][nt][1]), bias2), hzero));
            float w0c = w2s[col], w1c = w2s[col + 1];
            s0 += z01.x * w0c + z01.y * w1c;
            s1 += z23.x * w0c + z23.y * w1c;
        }
        int row = mt * 16 + arow;
        atomicAdd(&logits[row],     s0);
        atomicAdd(&logits[row + 8], s1);
    }
    __syncthreads();
    if (tid < 64)
        out[(size_t)(n0 + tid) * 16 + p] = 1.f / (1.f + expf(-logits[tid]));
}

// ---------------- launch ----------------
extern "C" void kernel_launch(void* const* d_in, const int* in_sizes, int n_in,
                              void* d_out, int out_size) {
    const float* X  = (const float*)d_in[0];
    const float* W0 = (const float*)d_in[1];
    const float* b0 = (const float*)d_in[2];
    const float* W1 = (const float*)d_in[3];
    const float* b1 = (const float*)d_in[4];
    const float* W2 = (const float*)d_in[5];
    const float* b2 = (const float*)d_in[6];
    float* out = (float*)d_out;

    prep_kernel<<<10240, 256>>>(X, W0, W1);

    cudaFuncSetAttribute(mlp_kernel, cudaFuncAttributeMaxDynamicSharedMemorySize, SMEM_SZ);
    mlp_kernel<<<dim3(P_PART, NENT / 64), 256, SMEM_SZ>>>(b0, b1, W2, b2, out);
}